// round 15
// baseline (speedup 1.0000x reference)
#include <cuda_runtime.h>
#include <cuda_bf16.h>
#include <cstdint>

#define Bb 16
#define Nn 8192
#define Gg 512
#define Kk 32
#define Dd 384
#define NPTS (Bb*Gg*Kk)      // 262144 grouped points
#define NBG  (Bb*Gg)         // 8192 groups

#define F_INF __int_as_float(0x7f800000)

// ---------------- static device scratch (no runtime allocation) ----------------
__device__ float  g_centers[NBG*3];
__device__ __align__(16) float g_grouped[NPTS*3];
__device__ float  g_xpart[NBG*9];
__device__ double g_xstats[9];
__device__ float  g_W1f[128*4];                 // folded layer1: (w0,w1,w2,bias)
__device__ __align__(16) float g_h2[(size_t)NPTS*256];   // 268 MB intermediate
__device__ float  g_h2sum[256*2048];
__device__ float  g_h2sq[256*2048];
__device__ float  g_bn2[512];                   // [0:256) scale, [256:512) shift
__device__ __align__(16) unsigned short g_W2hi[256*128];
__device__ __align__(16) unsigned short g_W2lo[256*128];
__device__ __align__(16) unsigned short g_W3hi[384*256];
__device__ __align__(16) unsigned short g_W3lo[384*256];
__device__ __align__(16) unsigned short g_Ahi[(size_t)NPTS*256];  // 134 MB pre-split act
__device__ __align__(16) unsigned short g_Alo[(size_t)NPTS*256];  // 134 MB

// ---------------- mma.sync / ldmatrix helpers (sm_80+ portable) ----------------
__device__ __forceinline__ uint32_t smem_u32(const void* p) {
    uint32_t a;
    asm("{ .reg .u64 t; cvta.to.shared.u64 t, %1; cvt.u32.u64 %0, t; }" : "=r"(a) : "l"(p));
    return a;
}
__device__ __forceinline__ void ldsm4(uint32_t r[4], uint32_t addr) {
    asm volatile("ldmatrix.sync.aligned.m8n8.x4.shared.b16 {%0,%1,%2,%3}, [%4];"
                 : "=r"(r[0]), "=r"(r[1]), "=r"(r[2]), "=r"(r[3]) : "r"(addr));
}
__device__ __forceinline__ void mma_bf16(float c[4], const uint32_t a[4],
                                         uint32_t b0, uint32_t b1) {
    asm volatile(
        "mma.sync.aligned.m16n8k16.row.col.f32.bf16.bf16.f32 "
        "{%0,%1,%2,%3}, {%4,%5,%6,%7}, {%8,%9}, {%0,%1,%2,%3};"
        : "+f"(c[0]), "+f"(c[1]), "+f"(c[2]), "+f"(c[3])
        : "r"(a[0]), "r"(a[1]), "r"(a[2]), "r"(a[3]), "r"(b0), "r"(b1));
}

// ============================================================
// Kernel: split weights into bf16 hi/lo. which: 0 = W2, 1 = W3.
// ============================================================
__global__ void prep_split_kernel(const float* __restrict__ src, int n, int which, int base) {
    int i = base + blockIdx.x*256 + threadIdx.x;
    if (i >= n) return;
    float v = src[i];
    __nv_bfloat16 h = __float2bfloat16_rn(v);
    float r = v - __bfloat162float(h);
    __nv_bfloat16 l = __float2bfloat16_rn(r);
    if (which == 0) { g_W2hi[i] = __bfloat16_as_ushort(h); g_W2lo[i] = __bfloat16_as_ushort(l); }
    else            { g_W3hi[i] = __bfloat16_as_ushort(h); g_W3lo[i] = __bfloat16_as_ushort(l); }
}

// ============================================================
// Kernel: farthest point sampling (R14 single-barrier version).
// ============================================================
__global__ __launch_bounds__(512) void fps_kernel(const float* __restrict__ pc,
                                                  float* __restrict__ out_centers) {
    int b = blockIdx.x;
    const float* p = pc + (size_t)b*Nn*3;
    int t = threadIdx.x;
    int lane = t & 31;

    __shared__ unsigned long long s_pk[Gg];
    for (int i = t; i < Gg; i += 512) s_pk[i] = 0ull;

    float px[16], py[16], pz[16], dist[16];
#pragma unroll
    for (int j = 0; j < 16; j++) {
        int idx = t + j*512;
        px[j] = p[idx*3+0]; py[j] = p[idx*3+1]; pz[j] = p[idx*3+2];
        dist[j] = F_INF;
    }

    float cx = p[0], cy = p[1], cz = p[2];
    if (t == 0) {
        int o = (b*Gg + 0)*3;
        g_centers[o] = cx; g_centers[o+1] = cy; g_centers[o+2] = cz;
        out_centers[o] = cx; out_centers[o+1] = cy; out_centers[o+2] = cz;
    }
    __syncthreads();

    for (int g = 1; g < Gg; g++) {
        float best = -1.0f; int bi = 0;
#pragma unroll
        for (int j = 0; j < 16; j++) {
            float dx = px[j]-cx, dy = py[j]-cy, dz = pz[j]-cz;
            float d = __fadd_rn(__fadd_rn(__fmul_rn(dx,dx), __fmul_rn(dy,dy)), __fmul_rn(dz,dz));
            float nd = fminf(dist[j], d);
            dist[j] = nd;
            if (nd > best) { best = nd; bi = t + j*512; }
        }
#pragma unroll
        for (int o = 16; o; o >>= 1) {
            float ov = __shfl_down_sync(0xffffffffu, best, o);
            int   oi = __shfl_down_sync(0xffffffffu, bi,   o);
            if (ov > best || (ov == best && oi < bi)) { best = ov; bi = oi; }
        }
        if (lane == 0) {
            unsigned long long pk =
                ((unsigned long long)__float_as_uint(best) << 32) | (unsigned)(~bi);
            atomicMax(&s_pk[g], pk);
        }
        __syncthreads();
        unsigned long long pk = s_pk[g];
        int sb = (int)(~(unsigned)pk);
        cx = __ldg(&p[sb*3+0]); cy = __ldg(&p[sb*3+1]); cz = __ldg(&p[sb*3+2]);
        if (t == 0) {
            int o = (b*Gg + g)*3;
            g_centers[o] = cx; g_centers[o+1] = cy; g_centers[o+2] = cz;
            out_centers[o] = cx; out_centers[o+1] = cy; out_centers[o+2] = cz;
        }
    }
}

// ============================================================
// Kernel: KNN + gather + 9-moment partials (R4 version — best measured).
// ============================================================
__global__ __launch_bounds__(256) void knn_kernel(const float* __restrict__ pc) {
    int bg = blockIdx.x;
    int b  = bg >> 9;
    const float* p = pc + (size_t)b*Nn*3;
    int t = threadIdx.x;

    float cx = g_centers[bg*3+0], cy = g_centers[bg*3+1], cz = g_centers[bg*3+2];

    float dl[32];
    float mv = F_INF; int mi = 0x3fffffff;
#pragma unroll
    for (int j = 0; j < 32; j++) {
        int idx = t + j*256;
        float dx = p[idx*3+0]-cx, dy = p[idx*3+1]-cy, dz = p[idx*3+2]-cz;
        float d = fmaf(dx,dx, fmaf(dy,dy, dz*dz));
        dl[j] = d;
        if (d < mv) { mv = d; mi = idx; }
    }

    __shared__ float s_v[8];
    __shared__ int   s_i[8];
    __shared__ int   s_sel[32];
    __shared__ int   s_b;

    for (int r = 0; r < 32; r++) {
        float v = mv; int id = mi;
#pragma unroll
        for (int o = 16; o; o >>= 1) {
            float ov = __shfl_down_sync(0xffffffffu, v,  o);
            int   oi = __shfl_down_sync(0xffffffffu, id, o);
            if (ov < v || (ov == v && oi < id)) { v = ov; id = oi; }
        }
        if ((t & 31) == 0) { s_v[t>>5] = v; s_i[t>>5] = id; }
        __syncthreads();
        if (t < 32) {
            v  = (t < 8) ? s_v[t] : F_INF;
            id = (t < 8) ? s_i[t] : 0x3fffffff;
#pragma unroll
            for (int o = 4; o; o >>= 1) {
                float ov = __shfl_down_sync(0xffffffffu, v,  o);
                int   oi = __shfl_down_sync(0xffffffffu, id, o);
                if (ov < v || (ov == v && oi < id)) { v = ov; id = oi; }
            }
            if (t == 0) { s_b = id; s_sel[r] = id; }
        }
        __syncthreads();
        int best = s_b;
        if ((best & 255) == t) {
#pragma unroll
            for (int j = 0; j < 32; j++) if (t + j*256 == best) dl[j] = F_INF;
            mv = F_INF; mi = 0x3fffffff;
#pragma unroll
            for (int j = 0; j < 32; j++) { if (dl[j] < mv) { mv = dl[j]; mi = t + j*256; } }
        }
        __syncthreads();
    }

    if (t < 32) {
        int pi = s_sel[t];
        float gx = p[pi*3+0]-cx, gy = p[pi*3+1]-cy, gz = p[pi*3+2]-cz;
        int go = (bg*32 + t)*3;
        g_grouped[go+0] = gx; g_grouped[go+1] = gy; g_grouped[go+2] = gz;
        float s[9] = {gx, gy, gz, gx*gx, gy*gy, gz*gz, gx*gy, gx*gz, gy*gz};
#pragma unroll
        for (int q = 0; q < 9; q++) {
#pragma unroll
            for (int o = 16; o; o >>= 1) s[q] += __shfl_down_sync(0xffffffffu, s[q], o);
        }
        if (t == 0) {
#pragma unroll
            for (int q = 0; q < 9; q++) g_xpart[bg*9 + q] = s[q];
        }
    }
}

// ============================================================
// Kernel: reduce x-moment partials (9 blocks)
// ============================================================
__global__ __launch_bounds__(256) void reduce_x_kernel() {
    __shared__ double sm[256];
    int s = blockIdx.x;
    double a = 0.0;
    for (int i = threadIdx.x; i < NBG; i += 256) a += (double)g_xpart[i*9 + s];
    sm[threadIdx.x] = a; __syncthreads();
    for (int o = 128; o; o >>= 1) {
        if (threadIdx.x < o) sm[threadIdx.x] += sm[threadIdx.x + o];
        __syncthreads();
    }
    if (threadIdx.x == 0) g_xstats[s] = sm[0];
}

// ============================================================
// Kernel: fold BN1 exactly into layer-1 affine
// ============================================================
__global__ void fold1_kernel(const float* __restrict__ W1, const float* __restrict__ b1,
                             const float* __restrict__ g1, const float* __restrict__ be1) {
    int d = threadIdx.x;
    double inv = 1.0 / (double)NPTS;
    double Ex = g_xstats[0]*inv, Ey = g_xstats[1]*inv, Ez = g_xstats[2]*inv;
    double Cxx = g_xstats[3]*inv - Ex*Ex;
    double Cyy = g_xstats[4]*inv - Ey*Ey;
    double Czz = g_xstats[5]*inv - Ez*Ez;
    double Cxy = g_xstats[6]*inv - Ex*Ey;
    double Cxz = g_xstats[7]*inv - Ex*Ez;
    double Cyz = g_xstats[8]*inv - Ey*Ez;
    double w0 = W1[d*3+0], w1 = W1[d*3+1], w2 = W1[d*3+2];
    double mu  = w0*Ex + w1*Ey + w2*Ez + (double)b1[d];
    double var = w0*w0*Cxx + w1*w1*Cyy + w2*w2*Czz + 2.0*(w0*w1*Cxy + w0*w2*Cxz + w1*w2*Cyz);
    if (var < 0.0) var = 0.0;
    double sc = (double)g1[d] / sqrt(var + 1e-5);
    g_W1f[d*4+0] = (float)(w0*sc);
    g_W1f[d*4+1] = (float)(w1*sc);
    g_W1f[d*4+2] = (float)(w2*sc);
    g_W1f[d*4+3] = (float)((double)b1[d]*sc + (double)be1[d] - mu*sc);
}

// ---------------- shared MMA tile constants ----------------
#define LDA 40              // bf16 elements per smem row (32 + 8 pad) -> 80B stride
__device__ __forceinline__ void split_store(char* hi, char* lo, uint32_t boff,
                                            float a0, float a1, float a2, float a3) {
    __nv_bfloat16 h0 = __float2bfloat16_rn(a0), h1 = __float2bfloat16_rn(a1);
    __nv_bfloat16 h2 = __float2bfloat16_rn(a2), h3 = __float2bfloat16_rn(a3);
    __nv_bfloat16 l0 = __float2bfloat16_rn(a0 - __bfloat162float(h0));
    __nv_bfloat16 l1 = __float2bfloat16_rn(a1 - __bfloat162float(h1));
    __nv_bfloat16 l2 = __float2bfloat16_rn(a2 - __bfloat162float(h2));
    __nv_bfloat16 l3 = __float2bfloat16_rn(a3 - __bfloat162float(h3));
    uint32_t hA = ((uint32_t)__bfloat16_as_ushort(h1) << 16) | __bfloat16_as_ushort(h0);
    uint32_t hB = ((uint32_t)__bfloat16_as_ushort(h3) << 16) | __bfloat16_as_ushort(h2);
    uint32_t lA = ((uint32_t)__bfloat16_as_ushort(l1) << 16) | __bfloat16_as_ushort(l0);
    uint32_t lB = ((uint32_t)__bfloat16_as_ushort(l3) << 16) | __bfloat16_as_ushort(l2);
    *(uint2*)(hi + boff) = make_uint2(hA, hB);
    *(uint2*)(lo + boff) = make_uint2(lA, lB);
}

// ============================================================
// Kernel: pass A on mma.sync bf16 3-split (R4 configuration).
// ============================================================
__global__ __launch_bounds__(256) void passA_mma(void) {
    __shared__ __align__(16) unsigned short sAh[128*LDA], sAl[128*LDA];
    __shared__ __align__(16) unsigned short sBh[64*LDA],  sBl[64*LDA];
    __shared__ float s_w1[512];
    __shared__ float s_g[384];
    __shared__ float s_redS[256], s_redQ[256];

    int tid = threadIdx.x, lane = tid & 31, wid = tid >> 5;
    int wm = wid >> 1, wn = wid & 1;
    int cb = blockIdx.x;            // 0..3
    int rb = blockIdx.y;            // 0..2047
    int r0 = rb*128, c0 = cb*64;

    for (int i = tid; i < 384; i += 256) s_g[i] = g_grouped[(size_t)r0*3 + i];
    s_w1[tid] = g_W1f[tid]; s_w1[tid+256] = g_W1f[tid+256];

    float acc[2][4][4];
#pragma unroll
    for (int a = 0; a < 2; a++)
#pragma unroll
        for (int b = 0; b < 4; b++)
#pragma unroll
            for (int c = 0; c < 4; c++) acc[a][b][c] = 0.f;

    uint32_t aHiB = smem_u32(sAh) + ((wm*32 + (lane & 15))*LDA + ((lane >> 4)*8))*2;
    uint32_t aLoB = smem_u32(sAl) + ((wm*32 + (lane & 15))*LDA + ((lane >> 4)*8))*2;
    uint32_t bHiB = smem_u32(sBh) + ((wn*32 + (lane & 15))*LDA + ((lane >> 4)*8))*2;
    uint32_t bLoB = smem_u32(sBl) + ((wn*32 + (lane & 15))*LDA + ((lane >> 4)*8))*2;

#pragma unroll 1
    for (int kc = 0; kc < 4; kc++) {
        __syncthreads();
        int k0 = kc*32;
#pragma unroll
        for (int i = 0; i < 4; i++) {
            int idx = i*256 + tid;
            int row = idx >> 3;
            int ch4 = (idx & 7)*4;
            float gx = s_g[row*3+0], gy = s_g[row*3+1], gz = s_g[row*3+2];
            float v[4];
#pragma unroll
            for (int q = 0; q < 4; q++) {
                int c = k0 + ch4 + q;
                v[q] = fmaxf(s_w1[c*4+0]*gx + s_w1[c*4+1]*gy + s_w1[c*4+2]*gz + s_w1[c*4+3], 0.f);
            }
            split_store((char*)sAh, (char*)sAl, (uint32_t)(row*LDA + ch4)*2, v[0], v[1], v[2], v[3]);
        }
        {
            int row = tid >> 2, seg = tid & 3;
            uint4 vh = *(const uint4*)&g_W2hi[(c0 + row)*128 + k0 + seg*8];
            uint4 vl = *(const uint4*)&g_W2lo[(c0 + row)*128 + k0 + seg*8];
            *(uint4*)((char*)sBh + row*LDA*2 + seg*16) = vh;
            *(uint4*)((char*)sBl + row*LDA*2 + seg*16) = vl;
        }
        __syncthreads();

#pragma unroll
        for (int k16 = 0; k16 < 2; k16++) {
            uint32_t ah[2][4], al[2][4], bh[2][4], bl[2][4];
#pragma unroll
            for (int mt = 0; mt < 2; mt++) {
                ldsm4(ah[mt], aHiB + mt*16*LDA*2 + k16*32);
                ldsm4(al[mt], aLoB + mt*16*LDA*2 + k16*32);
            }
#pragma unroll
            for (int np = 0; np < 2; np++) {
                ldsm4(bh[np], bHiB + np*16*LDA*2 + k16*32);
                ldsm4(bl[np], bLoB + np*16*LDA*2 + k16*32);
            }
#pragma unroll
            for (int mt = 0; mt < 2; mt++)
#pragma unroll
                for (int np = 0; np < 2; np++) {
                    mma_bf16(acc[mt][np*2+0], ah[mt], bh[np][0], bh[np][2]);
                    mma_bf16(acc[mt][np*2+1], ah[mt], bh[np][1], bh[np][3]);
                    mma_bf16(acc[mt][np*2+0], al[mt], bh[np][0], bh[np][2]);
                    mma_bf16(acc[mt][np*2+1], al[mt], bh[np][1], bh[np][3]);
                    mma_bf16(acc[mt][np*2+0], ah[mt], bl[np][0], bl[np][2]);
                    mma_bf16(acc[mt][np*2+1], ah[mt], bl[np][1], bl[np][3]);
                }
        }
    }

    int rbase = r0 + wm*32 + (lane >> 2);
    int cbase = c0 + wn*32 + 2*(lane & 3);
#pragma unroll
    for (int mt = 0; mt < 2; mt++)
#pragma unroll
        for (int nt = 0; nt < 4; nt++) {
            int row = rbase + mt*16;
            int col = cbase + nt*8;
            *(float2*)&g_h2[(size_t)row*256 + col]     = make_float2(acc[mt][nt][0], acc[mt][nt][1]);
            *(float2*)&g_h2[(size_t)(row+8)*256 + col] = make_float2(acc[mt][nt][2], acc[mt][nt][3]);
        }
#pragma unroll
    for (int nt = 0; nt < 4; nt++) {
        float s0 = 0.f, s1 = 0.f, q0 = 0.f, q1 = 0.f;
#pragma unroll
        for (int mt = 0; mt < 2; mt++) {
            s0 += acc[mt][nt][0] + acc[mt][nt][2];
            s1 += acc[mt][nt][1] + acc[mt][nt][3];
            q0 += acc[mt][nt][0]*acc[mt][nt][0] + acc[mt][nt][2]*acc[mt][nt][2];
            q1 += acc[mt][nt][1]*acc[mt][nt][1] + acc[mt][nt][3]*acc[mt][nt][3];
        }
#pragma unroll
        for (int off = 4; off < 32; off <<= 1) {
            s0 += __shfl_xor_sync(0xffffffffu, s0, off);
            s1 += __shfl_xor_sync(0xffffffffu, s1, off);
            q0 += __shfl_xor_sync(0xffffffffu, q0, off);
            q1 += __shfl_xor_sync(0xffffffffu, q1, off);
        }
        if (lane < 4) {
            int cl = wn*32 + nt*8 + 2*lane;
            s_redS[wm*64 + cl] = s0;   s_redS[wm*64 + cl + 1] = s1;
            s_redQ[wm*64 + cl] = q0;   s_redQ[wm*64 + cl + 1] = q1;
        }
    }
    __syncthreads();
    if (tid < 64) {
        float S = 0.f, Q = 0.f;
#pragma unroll
        for (int w = 0; w < 4; w++) { S += s_redS[w*64 + tid]; Q += s_redQ[w*64 + tid]; }
        g_h2sum[(c0 + tid)*2048 + rb] = S;
        g_h2sq [(c0 + tid)*2048 + rb] = Q;
    }
}

// ============================================================
// Kernel: BN2 stats reduce
// ============================================================
__global__ __launch_bounds__(256) void bn2_kernel(const float* __restrict__ g2,
                                                  const float* __restrict__ be2) {
    __shared__ double sm[256];
    __shared__ double sq[256];
    int ch = blockIdx.x;
    double a = 0.0, q = 0.0;
    for (int i = threadIdx.x; i < 2048; i += 256) {
        a += (double)g_h2sum[ch*2048 + i];
        q += (double)g_h2sq[ch*2048 + i];
    }
    sm[threadIdx.x] = a; sq[threadIdx.x] = q; __syncthreads();
    for (int o = 128; o; o >>= 1) {
        if (threadIdx.x < o) { sm[threadIdx.x] += sm[threadIdx.x+o]; sq[threadIdx.x] += sq[threadIdx.x+o]; }
        __syncthreads();
    }
    if (threadIdx.x == 0) {
        double mu  = sm[0] / (double)NPTS;
        double var = sq[0] / (double)NPTS - mu*mu;
        if (var < 0.0) var = 0.0;
        double sc = (double)g2[ch] / sqrt(var + 1e-5);
        g_bn2[ch]       = (float)sc;
        g_bn2[256 + ch] = (float)((double)be2[ch] - mu*sc);
    }
}

// ============================================================
// Kernel: bn2+relu+bf16-split of h2, done ONCE (removes the 6x
// redundant per-column-block transform from passB's A-fill).
// Each thread: 8 channels of one row. Values identical to the
// previous in-passB computation (same expressions).
// ============================================================
__global__ __launch_bounds__(256) void bnsplit_kernel(void) {
    __shared__ float s_bn[512];
    int tid = threadIdx.x;
    s_bn[tid] = g_bn2[tid]; s_bn[tid+256] = g_bn2[tid+256];
    __syncthreads();

    size_t i = (size_t)blockIdx.x*256 + tid;     // 8.39M threads
    size_t base = i*8;
    int ch0 = (int)(base & 255);

    float4 h0 = *(const float4*)&g_h2[base];
    float4 h1 = *(const float4*)&g_h2[base + 4];
    float a[8];
    a[0] = fmaxf(h0.x*s_bn[ch0+0] + s_bn[256+ch0+0], 0.f);
    a[1] = fmaxf(h0.y*s_bn[ch0+1] + s_bn[256+ch0+1], 0.f);
    a[2] = fmaxf(h0.z*s_bn[ch0+2] + s_bn[256+ch0+2], 0.f);
    a[3] = fmaxf(h0.w*s_bn[ch0+3] + s_bn[256+ch0+3], 0.f);
    a[4] = fmaxf(h1.x*s_bn[ch0+4] + s_bn[256+ch0+4], 0.f);
    a[5] = fmaxf(h1.y*s_bn[ch0+5] + s_bn[256+ch0+5], 0.f);
    a[6] = fmaxf(h1.z*s_bn[ch0+6] + s_bn[256+ch0+6], 0.f);
    a[7] = fmaxf(h1.w*s_bn[ch0+7] + s_bn[256+ch0+7], 0.f);

    unsigned short hi[8], lo[8];
#pragma unroll
    for (int q = 0; q < 8; q++) {
        __nv_bfloat16 h = __float2bfloat16_rn(a[q]);
        __nv_bfloat16 l = __float2bfloat16_rn(a[q] - __bfloat162float(h));
        hi[q] = __bfloat16_as_ushort(h);
        lo[q] = __bfloat16_as_ushort(l);
    }
    *(uint4*)&g_Ahi[base] = *(uint4*)hi;
    *(uint4*)&g_Alo[base] = *(uint4*)lo;
}

// ============================================================
// Kernel: pass B on mma.sync bf16 3-split; A-fill is now a pure
// copy from pre-split g_Ahi/g_Alo (no cvts, no fp32 loads).
// ============================================================
__global__ __launch_bounds__(256) void passB_mma(const float* __restrict__ b3,
                                                 float* __restrict__ out_tokens) {
    __shared__ __align__(16) unsigned short sAh[128*LDA], sAl[128*LDA];
    __shared__ __align__(16) unsigned short sBh[64*LDA],  sBl[64*LDA];

    int tid = threadIdx.x, lane = tid & 31, wid = tid >> 5;
    int wm = wid >> 1, wn = wid & 1;
    int cb = blockIdx.x;            // 0..5
    int rb = blockIdx.y;            // 0..2047
    int r0 = rb*128, c0 = cb*64;

    float acc[2][4][4];
#pragma unroll
    for (int a = 0; a < 2; a++)
#pragma unroll
        for (int b = 0; b < 4; b++)
#pragma unroll
            for (int c = 0; c < 4; c++) acc[a][b][c] = 0.f;

    uint32_t aHiB = smem_u32(sAh) + ((wm*32 + (lane & 15))*LDA + ((lane >> 4)*8))*2;
    uint32_t aLoB = smem_u32(sAl) + ((wm*32 + (lane & 15))*LDA + ((lane >> 4)*8))*2;
    uint32_t bHiB = smem_u32(sBh) + ((wn*32 + (lane & 15))*LDA + ((lane >> 4)*8))*2;
    uint32_t bLoB = smem_u32(sBl) + ((wn*32 + (lane & 15))*LDA + ((lane >> 4)*8))*2;

#pragma unroll 1
    for (int kc = 0; kc < 8; kc++) {
        __syncthreads();
        int k0 = kc*32;
        // A fill: copy pre-split activations. 128 rows x 32 ch.
#pragma unroll
        for (int i = 0; i < 4; i++) {
            int idx = i*256 + tid;
            int row = idx >> 3;
            int q4  = (idx & 7)*4;
            size_t gb = (size_t)(r0 + row)*256 + k0 + q4;
            uint2 vh = *(const uint2*)&g_Ahi[gb];
            uint2 vl = *(const uint2*)&g_Alo[gb];
            uint32_t boff = (uint32_t)(row*LDA + q4)*2;
            *(uint2*)((char*)sAh + boff) = vh;
            *(uint2*)((char*)sAl + boff) = vl;
        }
        // B fill: W3 slice rows c0..c0+63, k slice
        {
            int row = tid >> 2, seg = tid & 3;
            uint4 vh = *(const uint4*)&g_W3hi[(c0 + row)*256 + k0 + seg*8];
            uint4 vl = *(const uint4*)&g_W3lo[(c0 + row)*256 + k0 + seg*8];
            *(uint4*)((char*)sBh + row*LDA*2 + seg*16) = vh;
            *(uint4*)((char*)sBl + row*LDA*2 + seg*16) = vl;
        }
        __syncthreads();

#pragma unroll
        for (int k16 = 0; k16 < 2; k16++) {
            uint32_t ah[2][4], al[2][4], bh[2][4], bl[2][4];
#pragma unroll
            for (int mt = 0; mt < 2; mt++) {
                ldsm4(ah[mt], aHiB + mt*16*LDA*2 + k16*32);
                ldsm4(al[mt], aLoB + mt*16*LDA*2 + k16*32);
            }
#pragma unroll
            for (int np = 0; np < 2; np++) {
                ldsm4(bh[np], bHiB + np*16*LDA*2 + k16*32);
                ldsm4(bl[np], bLoB + np*16*LDA*2 + k16*32);
            }
#pragma unroll
            for (int mt = 0; mt < 2; mt++)
#pragma unroll
                for (int np = 0; np < 2; np++) {
                    mma_bf16(acc[mt][np*2+0], ah[mt], bh[np][0], bh[np][2]);
                    mma_bf16(acc[mt][np*2+1], ah[mt], bh[np][1], bh[np][3]);
                    mma_bf16(acc[mt][np*2+0], al[mt], bh[np][0], bh[np][2]);
                    mma_bf16(acc[mt][np*2+1], al[mt], bh[np][1], bh[np][3]);
                    mma_bf16(acc[mt][np*2+0], ah[mt], bl[np][0], bl[np][2]);
                    mma_bf16(acc[mt][np*2+1], ah[mt], bl[np][1], bl[np][3]);
                }
        }
    }

    int bg = rb*4 + wm;
#pragma unroll
    for (int nt = 0; nt < 4; nt++) {
        float m0 = fmaxf(fmaxf(acc[0][nt][0], acc[0][nt][2]), fmaxf(acc[1][nt][0], acc[1][nt][2]));
        float m1 = fmaxf(fmaxf(acc[0][nt][1], acc[0][nt][3]), fmaxf(acc[1][nt][1], acc[1][nt][3]));
#pragma unroll
        for (int off = 4; off < 32; off <<= 1) {
            m0 = fmaxf(m0, __shfl_xor_sync(0xffffffffu, m0, off));
            m1 = fmaxf(m1, __shfl_xor_sync(0xffffffffu, m1, off));
        }
        if (lane < 4) {
            int col = c0 + wn*32 + nt*8 + 2*lane;
            out_tokens[(size_t)bg*Dd + col]     = m0 + b3[col];
            out_tokens[(size_t)bg*Dd + col + 1] = m1 + b3[col + 1];
        }
    }
}

// ============================================================
extern "C" void kernel_launch(void* const* d_in, const int* in_sizes, int n_in,
                              void* d_out, int out_size) {
    const float* pc  = (const float*)d_in[0];
    const float* W1  = (const float*)d_in[1];
    const float* b1  = (const float*)d_in[2];
    const float* g1  = (const float*)d_in[3];
    const float* be1 = (const float*)d_in[4];
    const float* W2  = (const float*)d_in[5];
    // d_in[6] = b2 (cancels under BN2)
    const float* g2  = (const float*)d_in[7];
    const float* be2 = (const float*)d_in[8];
    const float* W3  = (const float*)d_in[9];
    const float* b3  = (const float*)d_in[10];

    float* out_tokens  = (float*)d_out;
    float* out_centers = (float*)d_out + (size_t)Bb*Gg*Dd;

    // knn in profiled slot #4
    prep_split_kernel<<<128, 256>>>(W2, 256*128, 0, 0);
    prep_split_kernel<<<384, 256>>>(W3, 384*256, 1, 0);
    fps_kernel<<<Bb, 512>>>(pc, out_centers);
    knn_kernel<<<NBG, 256>>>(pc);                        // launch #4 -> profiled
    reduce_x_kernel<<<9, 256>>>();
    fold1_kernel<<<1, 128>>>(W1, b1, g1, be1);
    passA_mma<<<dim3(4, 2048), 256>>>();
    bn2_kernel<<<256, 256>>>(g2, be2);
    bnsplit_kernel<<<32768, 256>>>();
    passB_mma<<<dim3(6, 2048), 256>>>(b3, out_tokens);
}

// round 16
// speedup vs baseline: 1.0187x; 1.0187x over previous
#include <cuda_runtime.h>
#include <cuda_bf16.h>
#include <cstdint>

#define Bb 16
#define Nn 8192
#define Gg 512
#define Kk 32
#define Dd 384
#define NPTS (Bb*Gg*Kk)      // 262144 grouped points
#define NBG  (Bb*Gg)         // 8192 groups

#define F_INF __int_as_float(0x7f800000)

// ---------------- static device scratch (no runtime allocation) ----------------
__device__ float  g_centers[NBG*3];
__device__ __align__(16) float g_grouped[NPTS*3];
__device__ float  g_xpart[NBG*9];
__device__ double g_xstats[9];
__device__ float  g_W1f[128*4];                 // folded layer1: (w0,w1,w2,bias)
__device__ __align__(16) float g_h2[(size_t)NPTS*256];   // 268 MB intermediate
__device__ float  g_h2sum[256*2048];
__device__ float  g_h2sq[256*2048];
__device__ float  g_bn2[512];                   // [0:256) scale, [256:512) shift
__device__ __align__(16) unsigned short g_W2hi[256*128];
__device__ __align__(16) unsigned short g_W2lo[256*128];
__device__ __align__(16) unsigned short g_W3hi[384*256];
__device__ __align__(16) unsigned short g_W3lo[384*256];

// ---------------- mma.sync / ldmatrix helpers (sm_80+ portable) ----------------
__device__ __forceinline__ uint32_t smem_u32(const void* p) {
    uint32_t a;
    asm("{ .reg .u64 t; cvta.to.shared.u64 t, %1; cvt.u32.u64 %0, t; }" : "=r"(a) : "l"(p));
    return a;
}
__device__ __forceinline__ void ldsm4(uint32_t r[4], uint32_t addr) {
    asm volatile("ldmatrix.sync.aligned.m8n8.x4.shared.b16 {%0,%1,%2,%3}, [%4];"
                 : "=r"(r[0]), "=r"(r[1]), "=r"(r[2]), "=r"(r[3]) : "r"(addr));
}
__device__ __forceinline__ void mma_bf16(float c[4], const uint32_t a[4],
                                         uint32_t b0, uint32_t b1) {
    asm volatile(
        "mma.sync.aligned.m16n8k16.row.col.f32.bf16.bf16.f32 "
        "{%0,%1,%2,%3}, {%4,%5,%6,%7}, {%8,%9}, {%0,%1,%2,%3};"
        : "+f"(c[0]), "+f"(c[1]), "+f"(c[2]), "+f"(c[3])
        : "r"(a[0]), "r"(a[1]), "r"(a[2]), "r"(a[3]), "r"(b0), "r"(b1));
}

// ============================================================
// Kernel: split weights into bf16 hi/lo. which: 0 = W2, 1 = W3.
// ============================================================
__global__ void prep_split_kernel(const float* __restrict__ src, int n, int which, int base) {
    int i = base + blockIdx.x*256 + threadIdx.x;
    if (i >= n) return;
    float v = src[i];
    __nv_bfloat16 h = __float2bfloat16_rn(v);
    float r = v - __bfloat162float(h);
    __nv_bfloat16 l = __float2bfloat16_rn(r);
    if (which == 0) { g_W2hi[i] = __bfloat16_as_ushort(h); g_W2lo[i] = __bfloat16_as_ushort(l); }
    else            { g_W3hi[i] = __bfloat16_as_ushort(h); g_W3lo[i] = __bfloat16_as_ushort(l); }
}

// ============================================================
// Kernel: farthest point sampling (R14 single-barrier version).
// ============================================================
__global__ __launch_bounds__(512) void fps_kernel(const float* __restrict__ pc,
                                                  float* __restrict__ out_centers) {
    int b = blockIdx.x;
    const float* p = pc + (size_t)b*Nn*3;
    int t = threadIdx.x;
    int lane = t & 31;

    __shared__ unsigned long long s_pk[Gg];
    for (int i = t; i < Gg; i += 512) s_pk[i] = 0ull;

    float px[16], py[16], pz[16], dist[16];
#pragma unroll
    for (int j = 0; j < 16; j++) {
        int idx = t + j*512;
        px[j] = p[idx*3+0]; py[j] = p[idx*3+1]; pz[j] = p[idx*3+2];
        dist[j] = F_INF;
    }

    float cx = p[0], cy = p[1], cz = p[2];
    if (t == 0) {
        int o = (b*Gg + 0)*3;
        g_centers[o] = cx; g_centers[o+1] = cy; g_centers[o+2] = cz;
        out_centers[o] = cx; out_centers[o+1] = cy; out_centers[o+2] = cz;
    }
    __syncthreads();

    for (int g = 1; g < Gg; g++) {
        float best = -1.0f; int bi = 0;
#pragma unroll
        for (int j = 0; j < 16; j++) {
            float dx = px[j]-cx, dy = py[j]-cy, dz = pz[j]-cz;
            float d = __fadd_rn(__fadd_rn(__fmul_rn(dx,dx), __fmul_rn(dy,dy)), __fmul_rn(dz,dz));
            float nd = fminf(dist[j], d);
            dist[j] = nd;
            if (nd > best) { best = nd; bi = t + j*512; }
        }
#pragma unroll
        for (int o = 16; o; o >>= 1) {
            float ov = __shfl_down_sync(0xffffffffu, best, o);
            int   oi = __shfl_down_sync(0xffffffffu, bi,   o);
            if (ov > best || (ov == best && oi < bi)) { best = ov; bi = oi; }
        }
        if (lane == 0) {
            unsigned long long pk =
                ((unsigned long long)__float_as_uint(best) << 32) | (unsigned)(~bi);
            atomicMax(&s_pk[g], pk);
        }
        __syncthreads();
        unsigned long long pk = s_pk[g];
        int sb = (int)(~(unsigned)pk);
        cx = __ldg(&p[sb*3+0]); cy = __ldg(&p[sb*3+1]); cz = __ldg(&p[sb*3+2]);
        if (t == 0) {
            int o = (b*Gg + g)*3;
            g_centers[o] = cx; g_centers[o+1] = cy; g_centers[o+2] = cz;
            out_centers[o] = cx; out_centers[o+1] = cy; out_centers[o+2] = cz;
        }
    }
}

// ============================================================
// Kernel: KNN + gather + 9-moment partials (R4 version — best measured).
// ============================================================
__global__ __launch_bounds__(256) void knn_kernel(const float* __restrict__ pc) {
    int bg = blockIdx.x;
    int b  = bg >> 9;
    const float* p = pc + (size_t)b*Nn*3;
    int t = threadIdx.x;

    float cx = g_centers[bg*3+0], cy = g_centers[bg*3+1], cz = g_centers[bg*3+2];

    float dl[32];
    float mv = F_INF; int mi = 0x3fffffff;
#pragma unroll
    for (int j = 0; j < 32; j++) {
        int idx = t + j*256;
        float dx = p[idx*3+0]-cx, dy = p[idx*3+1]-cy, dz = p[idx*3+2]-cz;
        float d = fmaf(dx,dx, fmaf(dy,dy, dz*dz));
        dl[j] = d;
        if (d < mv) { mv = d; mi = idx; }
    }

    __shared__ float s_v[8];
    __shared__ int   s_i[8];
    __shared__ int   s_sel[32];
    __shared__ int   s_b;

    for (int r = 0; r < 32; r++) {
        float v = mv; int id = mi;
#pragma unroll
        for (int o = 16; o; o >>= 1) {
            float ov = __shfl_down_sync(0xffffffffu, v,  o);
            int   oi = __shfl_down_sync(0xffffffffu, id, o);
            if (ov < v || (ov == v && oi < id)) { v = ov; id = oi; }
        }
        if ((t & 31) == 0) { s_v[t>>5] = v; s_i[t>>5] = id; }
        __syncthreads();
        if (t < 32) {
            v  = (t < 8) ? s_v[t] : F_INF;
            id = (t < 8) ? s_i[t] : 0x3fffffff;
#pragma unroll
            for (int o = 4; o; o >>= 1) {
                float ov = __shfl_down_sync(0xffffffffu, v,  o);
                int   oi = __shfl_down_sync(0xffffffffu, id, o);
                if (ov < v || (ov == v && oi < id)) { v = ov; id = oi; }
            }
            if (t == 0) { s_b = id; s_sel[r] = id; }
        }
        __syncthreads();
        int best = s_b;
        if ((best & 255) == t) {
#pragma unroll
            for (int j = 0; j < 32; j++) if (t + j*256 == best) dl[j] = F_INF;
            mv = F_INF; mi = 0x3fffffff;
#pragma unroll
            for (int j = 0; j < 32; j++) { if (dl[j] < mv) { mv = dl[j]; mi = t + j*256; } }
        }
        __syncthreads();
    }

    if (t < 32) {
        int pi = s_sel[t];
        float gx = p[pi*3+0]-cx, gy = p[pi*3+1]-cy, gz = p[pi*3+2]-cz;
        int go = (bg*32 + t)*3;
        g_grouped[go+0] = gx; g_grouped[go+1] = gy; g_grouped[go+2] = gz;
        float s[9] = {gx, gy, gz, gx*gx, gy*gy, gz*gz, gx*gy, gx*gz, gy*gz};
#pragma unroll
        for (int q = 0; q < 9; q++) {
#pragma unroll
            for (int o = 16; o; o >>= 1) s[q] += __shfl_down_sync(0xffffffffu, s[q], o);
        }
        if (t == 0) {
#pragma unroll
            for (int q = 0; q < 9; q++) g_xpart[bg*9 + q] = s[q];
        }
    }
}

// ============================================================
// Kernel: reduce x-moment partials (9 blocks)
// ============================================================
__global__ __launch_bounds__(256) void reduce_x_kernel() {
    __shared__ double sm[256];
    int s = blockIdx.x;
    double a = 0.0;
    for (int i = threadIdx.x; i < NBG; i += 256) a += (double)g_xpart[i*9 + s];
    sm[threadIdx.x] = a; __syncthreads();
    for (int o = 128; o; o >>= 1) {
        if (threadIdx.x < o) sm[threadIdx.x] += sm[threadIdx.x + o];
        __syncthreads();
    }
    if (threadIdx.x == 0) g_xstats[s] = sm[0];
}

// ============================================================
// Kernel: fold BN1 exactly into layer-1 affine
// ============================================================
__global__ void fold1_kernel(const float* __restrict__ W1, const float* __restrict__ b1,
                             const float* __restrict__ g1, const float* __restrict__ be1) {
    int d = threadIdx.x;
    double inv = 1.0 / (double)NPTS;
    double Ex = g_xstats[0]*inv, Ey = g_xstats[1]*inv, Ez = g_xstats[2]*inv;
    double Cxx = g_xstats[3]*inv - Ex*Ex;
    double Cyy = g_xstats[4]*inv - Ey*Ey;
    double Czz = g_xstats[5]*inv - Ez*Ez;
    double Cxy = g_xstats[6]*inv - Ex*Ey;
    double Cxz = g_xstats[7]*inv - Ex*Ez;
    double Cyz = g_xstats[8]*inv - Ey*Ez;
    double w0 = W1[d*3+0], w1 = W1[d*3+1], w2 = W1[d*3+2];
    double mu  = w0*Ex + w1*Ey + w2*Ez + (double)b1[d];
    double var = w0*w0*Cxx + w1*w1*Cyy + w2*w2*Czz + 2.0*(w0*w1*Cxy + w0*w2*Cxz + w1*w2*Cyz);
    if (var < 0.0) var = 0.0;
    double sc = (double)g1[d] / sqrt(var + 1e-5);
    g_W1f[d*4+0] = (float)(w0*sc);
    g_W1f[d*4+1] = (float)(w1*sc);
    g_W1f[d*4+2] = (float)(w2*sc);
    g_W1f[d*4+3] = (float)((double)b1[d]*sc + (double)be1[d] - mu*sc);
}

// ---------------- shared MMA tile constants ----------------
#define LDA 40              // bf16 elements per smem row (32 + 8 pad) -> 80B stride
__device__ __forceinline__ void split_store(char* hi, char* lo, uint32_t boff,
                                            float a0, float a1, float a2, float a3) {
    __nv_bfloat16 h0 = __float2bfloat16_rn(a0), h1 = __float2bfloat16_rn(a1);
    __nv_bfloat16 h2 = __float2bfloat16_rn(a2), h3 = __float2bfloat16_rn(a3);
    __nv_bfloat16 l0 = __float2bfloat16_rn(a0 - __bfloat162float(h0));
    __nv_bfloat16 l1 = __float2bfloat16_rn(a1 - __bfloat162float(h1));
    __nv_bfloat16 l2 = __float2bfloat16_rn(a2 - __bfloat162float(h2));
    __nv_bfloat16 l3 = __float2bfloat16_rn(a3 - __bfloat162float(h3));
    uint32_t hA = ((uint32_t)__bfloat16_as_ushort(h1) << 16) | __bfloat16_as_ushort(h0);
    uint32_t hB = ((uint32_t)__bfloat16_as_ushort(h3) << 16) | __bfloat16_as_ushort(h2);
    uint32_t lA = ((uint32_t)__bfloat16_as_ushort(l1) << 16) | __bfloat16_as_ushort(l0);
    uint32_t lB = ((uint32_t)__bfloat16_as_ushort(l3) << 16) | __bfloat16_as_ushort(l2);
    *(uint2*)(hi + boff) = make_uint2(hA, hB);
    *(uint2*)(lo + boff) = make_uint2(lA, lB);
}

// ============================================================
// Kernel: pass A on mma.sync bf16 3-split (R4 configuration).
// ============================================================
__global__ __launch_bounds__(256) void passA_mma(void) {
    __shared__ __align__(16) unsigned short sAh[128*LDA], sAl[128*LDA];
    __shared__ __align__(16) unsigned short sBh[64*LDA],  sBl[64*LDA];
    __shared__ float s_w1[512];
    __shared__ float s_g[384];
    __shared__ float s_redS[256], s_redQ[256];

    int tid = threadIdx.x, lane = tid & 31, wid = tid >> 5;
    int wm = wid >> 1, wn = wid & 1;
    int cb = blockIdx.x;            // 0..3
    int rb = blockIdx.y;            // 0..2047
    int r0 = rb*128, c0 = cb*64;

    for (int i = tid; i < 384; i += 256) s_g[i] = g_grouped[(size_t)r0*3 + i];
    s_w1[tid] = g_W1f[tid]; s_w1[tid+256] = g_W1f[tid+256];

    float acc[2][4][4];
#pragma unroll
    for (int a = 0; a < 2; a++)
#pragma unroll
        for (int b = 0; b < 4; b++)
#pragma unroll
            for (int c = 0; c < 4; c++) acc[a][b][c] = 0.f;

    uint32_t aHiB = smem_u32(sAh) + ((wm*32 + (lane & 15))*LDA + ((lane >> 4)*8))*2;
    uint32_t aLoB = smem_u32(sAl) + ((wm*32 + (lane & 15))*LDA + ((lane >> 4)*8))*2;
    uint32_t bHiB = smem_u32(sBh) + ((wn*32 + (lane & 15))*LDA + ((lane >> 4)*8))*2;
    uint32_t bLoB = smem_u32(sBl) + ((wn*32 + (lane & 15))*LDA + ((lane >> 4)*8))*2;

#pragma unroll 1
    for (int kc = 0; kc < 4; kc++) {
        __syncthreads();
        int k0 = kc*32;
#pragma unroll
        for (int i = 0; i < 4; i++) {
            int idx = i*256 + tid;
            int row = idx >> 3;
            int ch4 = (idx & 7)*4;
            float gx = s_g[row*3+0], gy = s_g[row*3+1], gz = s_g[row*3+2];
            float v[4];
#pragma unroll
            for (int q = 0; q < 4; q++) {
                int c = k0 + ch4 + q;
                v[q] = fmaxf(s_w1[c*4+0]*gx + s_w1[c*4+1]*gy + s_w1[c*4+2]*gz + s_w1[c*4+3], 0.f);
            }
            split_store((char*)sAh, (char*)sAl, (uint32_t)(row*LDA + ch4)*2, v[0], v[1], v[2], v[3]);
        }
        {
            int row = tid >> 2, seg = tid & 3;
            uint4 vh = *(const uint4*)&g_W2hi[(c0 + row)*128 + k0 + seg*8];
            uint4 vl = *(const uint4*)&g_W2lo[(c0 + row)*128 + k0 + seg*8];
            *(uint4*)((char*)sBh + row*LDA*2 + seg*16) = vh;
            *(uint4*)((char*)sBl + row*LDA*2 + seg*16) = vl;
        }
        __syncthreads();

#pragma unroll
        for (int k16 = 0; k16 < 2; k16++) {
            uint32_t ah[2][4], al[2][4], bh[2][4], bl[2][4];
#pragma unroll
            for (int mt = 0; mt < 2; mt++) {
                ldsm4(ah[mt], aHiB + mt*16*LDA*2 + k16*32);
                ldsm4(al[mt], aLoB + mt*16*LDA*2 + k16*32);
            }
#pragma unroll
            for (int np = 0; np < 2; np++) {
                ldsm4(bh[np], bHiB + np*16*LDA*2 + k16*32);
                ldsm4(bl[np], bLoB + np*16*LDA*2 + k16*32);
            }
#pragma unroll
            for (int mt = 0; mt < 2; mt++)
#pragma unroll
                for (int np = 0; np < 2; np++) {
                    mma_bf16(acc[mt][np*2+0], ah[mt], bh[np][0], bh[np][2]);
                    mma_bf16(acc[mt][np*2+1], ah[mt], bh[np][1], bh[np][3]);
                    mma_bf16(acc[mt][np*2+0], al[mt], bh[np][0], bh[np][2]);
                    mma_bf16(acc[mt][np*2+1], al[mt], bh[np][1], bh[np][3]);
                    mma_bf16(acc[mt][np*2+0], ah[mt], bl[np][0], bl[np][2]);
                    mma_bf16(acc[mt][np*2+1], ah[mt], bl[np][1], bl[np][3]);
                }
        }
    }

    int rbase = r0 + wm*32 + (lane >> 2);
    int cbase = c0 + wn*32 + 2*(lane & 3);
#pragma unroll
    for (int mt = 0; mt < 2; mt++)
#pragma unroll
        for (int nt = 0; nt < 4; nt++) {
            int row = rbase + mt*16;
            int col = cbase + nt*8;
            *(float2*)&g_h2[(size_t)row*256 + col]     = make_float2(acc[mt][nt][0], acc[mt][nt][1]);
            *(float2*)&g_h2[(size_t)(row+8)*256 + col] = make_float2(acc[mt][nt][2], acc[mt][nt][3]);
        }
#pragma unroll
    for (int nt = 0; nt < 4; nt++) {
        float s0 = 0.f, s1 = 0.f, q0 = 0.f, q1 = 0.f;
#pragma unroll
        for (int mt = 0; mt < 2; mt++) {
            s0 += acc[mt][nt][0] + acc[mt][nt][2];
            s1 += acc[mt][nt][1] + acc[mt][nt][3];
            q0 += acc[mt][nt][0]*acc[mt][nt][0] + acc[mt][nt][2]*acc[mt][nt][2];
            q1 += acc[mt][nt][1]*acc[mt][nt][1] + acc[mt][nt][3]*acc[mt][nt][3];
        }
#pragma unroll
        for (int off = 4; off < 32; off <<= 1) {
            s0 += __shfl_xor_sync(0xffffffffu, s0, off);
            s1 += __shfl_xor_sync(0xffffffffu, s1, off);
            q0 += __shfl_xor_sync(0xffffffffu, q0, off);
            q1 += __shfl_xor_sync(0xffffffffu, q1, off);
        }
        if (lane < 4) {
            int cl = wn*32 + nt*8 + 2*lane;
            s_redS[wm*64 + cl] = s0;   s_redS[wm*64 + cl + 1] = s1;
            s_redQ[wm*64 + cl] = q0;   s_redQ[wm*64 + cl + 1] = q1;
        }
    }
    __syncthreads();
    if (tid < 64) {
        float S = 0.f, Q = 0.f;
#pragma unroll
        for (int w = 0; w < 4; w++) { S += s_redS[w*64 + tid]; Q += s_redQ[w*64 + tid]; }
        g_h2sum[(c0 + tid)*2048 + rb] = S;
        g_h2sq [(c0 + tid)*2048 + rb] = Q;
    }
}

// ============================================================
// Kernel: BN2 stats reduce
// ============================================================
__global__ __launch_bounds__(256) void bn2_kernel(const float* __restrict__ g2,
                                                  const float* __restrict__ be2) {
    __shared__ double sm[256];
    __shared__ double sq[256];
    int ch = blockIdx.x;
    double a = 0.0, q = 0.0;
    for (int i = threadIdx.x; i < 2048; i += 256) {
        a += (double)g_h2sum[ch*2048 + i];
        q += (double)g_h2sq[ch*2048 + i];
    }
    sm[threadIdx.x] = a; sq[threadIdx.x] = q; __syncthreads();
    for (int o = 128; o; o >>= 1) {
        if (threadIdx.x < o) { sm[threadIdx.x] += sm[threadIdx.x+o]; sq[threadIdx.x] += sq[threadIdx.x+o]; }
        __syncthreads();
    }
    if (threadIdx.x == 0) {
        double mu  = sm[0] / (double)NPTS;
        double var = sq[0] / (double)NPTS - mu*mu;
        if (var < 0.0) var = 0.0;
        double sc = (double)g2[ch] / sqrt(var + 1e-5);
        g_bn2[ch]       = (float)sc;
        g_bn2[256 + ch] = (float)((double)be2[ch] - mu*sc);
    }
}

// ============================================================
// Kernel: pass B on mma.sync bf16 3-split, k-chunk widened to 64
// (two 32-col sub-tiles per stage) -> half the __syncthreads.
// Dynamic smem 61440 B. Values bit-identical to R14.
// ============================================================
#define PB_SMEM 61440
// dyn layout: Ah0 @0, Ah1 @10240, Al0 @20480, Al1 @30720,
//             Bh0 @40960, Bh1 @46080, Bl0 @51200, Bl1 @56320
__global__ __launch_bounds__(256) void passB_mma(const float* __restrict__ b3,
                                                 float* __restrict__ out_tokens) {
    extern __shared__ char dynsm[];
    __shared__ float s_bn[512];

    int tid = threadIdx.x, lane = tid & 31, wid = tid >> 5;
    int wm = wid >> 1, wn = wid & 1;
    int cb = blockIdx.x;            // 0..5
    int rb = blockIdx.y;            // 0..2047
    int r0 = rb*128, c0 = cb*64;

    s_bn[tid] = g_bn2[tid]; s_bn[tid+256] = g_bn2[tid+256];

    float acc[2][4][4];
#pragma unroll
    for (int a = 0; a < 2; a++)
#pragma unroll
        for (int b = 0; b < 4; b++)
#pragma unroll
            for (int c = 0; c < 4; c++) acc[a][b][c] = 0.f;

    uint32_t dynb = smem_u32(dynsm);
    uint32_t aOff = ((wm*32 + (lane & 15))*LDA + ((lane >> 4)*8))*2;
    uint32_t bOff = ((wn*32 + (lane & 15))*LDA + ((lane >> 4)*8))*2;

#pragma unroll 1
    for (int kc = 0; kc < 4; kc++) {
        __syncthreads();
        int k0 = kc*64;
        // A fill: bn2+relu+split. 128 rows x 64 ch -> 8 slots/thread of 4 ch.
#pragma unroll
        for (int i = 0; i < 8; i++) {
            int idx = i*256 + tid;           // 0..2047
            int row = idx >> 4;
            int c4  = (idx & 15)*4;          // 0..60
            float4 h = *(const float4*)&g_h2[(size_t)(r0 + row)*256 + k0 + c4];
            int ch = k0 + c4;
            float a0 = fmaxf(h.x*s_bn[ch+0] + s_bn[256+ch+0], 0.f);
            float a1 = fmaxf(h.y*s_bn[ch+1] + s_bn[256+ch+1], 0.f);
            float a2 = fmaxf(h.z*s_bn[ch+2] + s_bn[256+ch+2], 0.f);
            float a3 = fmaxf(h.w*s_bn[ch+3] + s_bn[256+ch+3], 0.f);
            int sub = c4 >> 5;               // 0 or 1
            int cin = c4 & 31;
            char* Ah = dynsm + sub*10240;
            char* Al = dynsm + 20480 + sub*10240;
            split_store(Ah, Al, (uint32_t)(row*LDA + cin)*2, a0, a1, a2, a3);
        }
        // B fill: W3 rows c0..c0+63, 64 k-cols -> 2 slots/thread of 8 cols.
#pragma unroll
        for (int s = 0; s < 2; s++) {
            int idx = s*256 + tid;           // 0..511
            int row = idx >> 3;              // 0..63
            int seg = idx & 7;               // 0..7 (col = seg*8)
            uint4 vh = *(const uint4*)&g_W3hi[(c0 + row)*256 + k0 + seg*8];
            uint4 vl = *(const uint4*)&g_W3lo[(c0 + row)*256 + k0 + seg*8];
            int sub = seg >> 2;
            int sin = seg & 3;
            *(uint4*)(dynsm + 40960 + sub*5120 + row*LDA*2 + sin*16) = vh;
            *(uint4*)(dynsm + 51200 + sub*5120 + row*LDA*2 + sin*16) = vl;
        }
        __syncthreads();

#pragma unroll
        for (int sub = 0; sub < 2; sub++) {
            uint32_t aHiB = dynb + sub*10240 + aOff;
            uint32_t aLoB = dynb + 20480 + sub*10240 + aOff;
            uint32_t bHiB = dynb + 40960 + sub*5120 + bOff;
            uint32_t bLoB = dynb + 51200 + sub*5120 + bOff;
#pragma unroll
            for (int k16 = 0; k16 < 2; k16++) {
                uint32_t ah[2][4], al[2][4], bh[2][4], bl[2][4];
#pragma unroll
                for (int mt = 0; mt < 2; mt++) {
                    ldsm4(ah[mt], aHiB + mt*16*LDA*2 + k16*32);
                    ldsm4(al[mt], aLoB + mt*16*LDA*2 + k16*32);
                }
#pragma unroll
                for (int np = 0; np < 2; np++) {
                    ldsm4(bh[np], bHiB + np*16*LDA*2 + k16*32);
                    ldsm4(bl[np], bLoB + np*16*LDA*2 + k16*32);
                }
#pragma unroll
                for (int mt = 0; mt < 2; mt++)
#pragma unroll
                    for (int np = 0; np < 2; np++) {
                        mma_bf16(acc[mt][np*2+0], ah[mt], bh[np][0], bh[np][2]);
                        mma_bf16(acc[mt][np*2+1], ah[mt], bh[np][1], bh[np][3]);
                        mma_bf16(acc[mt][np*2+0], al[mt], bh[np][0], bh[np][2]);
                        mma_bf16(acc[mt][np*2+1], al[mt], bh[np][1], bh[np][3]);
                        mma_bf16(acc[mt][np*2+0], ah[mt], bl[np][0], bl[np][2]);
                        mma_bf16(acc[mt][np*2+1], ah[mt], bl[np][1], bl[np][3]);
                    }
            }
        }
    }

    int bg = rb*4 + wm;
#pragma unroll
    for (int nt = 0; nt < 4; nt++) {
        float m0 = fmaxf(fmaxf(acc[0][nt][0], acc[0][nt][2]), fmaxf(acc[1][nt][0], acc[1][nt][2]));
        float m1 = fmaxf(fmaxf(acc[0][nt][1], acc[0][nt][3]), fmaxf(acc[1][nt][1], acc[1][nt][3]));
#pragma unroll
        for (int off = 4; off < 32; off <<= 1) {
            m0 = fmaxf(m0, __shfl_xor_sync(0xffffffffu, m0, off));
            m1 = fmaxf(m1, __shfl_xor_sync(0xffffffffu, m1, off));
        }
        if (lane < 4) {
            int col = c0 + wn*32 + nt*8 + 2*lane;
            out_tokens[(size_t)bg*Dd + col]     = m0 + b3[col];
            out_tokens[(size_t)bg*Dd + col + 1] = m1 + b3[col + 1];
        }
    }
}

// ============================================================
extern "C" void kernel_launch(void* const* d_in, const int* in_sizes, int n_in,
                              void* d_out, int out_size) {
    const float* pc  = (const float*)d_in[0];
    const float* W1  = (const float*)d_in[1];
    const float* b1  = (const float*)d_in[2];
    const float* g1  = (const float*)d_in[3];
    const float* be1 = (const float*)d_in[4];
    const float* W2  = (const float*)d_in[5];
    // d_in[6] = b2 (cancels under BN2)
    const float* g2  = (const float*)d_in[7];
    const float* be2 = (const float*)d_in[8];
    const float* W3  = (const float*)d_in[9];
    const float* b3  = (const float*)d_in[10];

    float* out_tokens  = (float*)d_out;
    float* out_centers = (float*)d_out + (size_t)Bb*Gg*Dd;

    static int attr_set = 0;
    if (!attr_set) {
        cudaFuncSetAttribute(passB_mma, cudaFuncAttributeMaxDynamicSharedMemorySize, PB_SMEM);
        attr_set = 1;
    }

    // knn in profiled slot #4
    prep_split_kernel<<<128, 256>>>(W2, 256*128, 0, 0);
    prep_split_kernel<<<384, 256>>>(W3, 384*256, 1, 0);
    fps_kernel<<<Bb, 512>>>(pc, out_centers);
    knn_kernel<<<NBG, 256>>>(pc);                        // launch #4 -> profiled
    reduce_x_kernel<<<9, 256>>>();
    fold1_kernel<<<1, 128>>>(W1, b1, g1, be1);
    passA_mma<<<dim3(4, 2048), 256>>>();
    bn2_kernel<<<256, 256>>>(g2, be2);
    passB_mma<<<dim3(6, 2048), 256, PB_SMEM>>>(b3, out_tokens);
}

// round 17
// speedup vs baseline: 1.0928x; 1.0728x over previous
#include <cuda_runtime.h>
#include <cuda_bf16.h>
#include <cstdint>

#define Bb 16
#define Nn 8192
#define Gg 512
#define Kk 32
#define Dd 384
#define NPTS (Bb*Gg*Kk)      // 262144 grouped points
#define NBG  (Bb*Gg)         // 8192 groups

#define F_INF __int_as_float(0x7f800000)

// ---------------- static device scratch (no runtime allocation) ----------------
__device__ float  g_centers[NBG*3];
__device__ __align__(16) float g_grouped[NPTS*3];
__device__ float  g_xpart[NBG*9];
__device__ double g_xstats[9];
__device__ float  g_W1f[128*4];                 // folded layer1: (w0,w1,w2,bias)
__device__ __align__(16) float g_h2[(size_t)NPTS*256];   // 268 MB intermediate
__device__ float  g_h2sum[256*2048];
__device__ float  g_h2sq[256*2048];
__device__ float  g_bn2[512];                   // [0:256) scale, [256:512) shift
__device__ __align__(16) unsigned short g_W2hi[256*128];
__device__ __align__(16) unsigned short g_W2lo[256*128];
__device__ __align__(16) unsigned short g_W3hi[384*256];
__device__ __align__(16) unsigned short g_W3lo[384*256];

// ---------------- mma.sync / ldmatrix helpers (sm_80+ portable) ----------------
__device__ __forceinline__ uint32_t smem_u32(const void* p) {
    uint32_t a;
    asm("{ .reg .u64 t; cvta.to.shared.u64 t, %1; cvt.u32.u64 %0, t; }" : "=r"(a) : "l"(p));
    return a;
}
__device__ __forceinline__ void ldsm4(uint32_t r[4], uint32_t addr) {
    asm volatile("ldmatrix.sync.aligned.m8n8.x4.shared.b16 {%0,%1,%2,%3}, [%4];"
                 : "=r"(r[0]), "=r"(r[1]), "=r"(r[2]), "=r"(r[3]) : "r"(addr));
}
__device__ __forceinline__ void mma_bf16(float c[4], const uint32_t a[4],
                                         uint32_t b0, uint32_t b1) {
    asm volatile(
        "mma.sync.aligned.m16n8k16.row.col.f32.bf16.bf16.f32 "
        "{%0,%1,%2,%3}, {%4,%5,%6,%7}, {%8,%9}, {%0,%1,%2,%3};"
        : "+f"(c[0]), "+f"(c[1]), "+f"(c[2]), "+f"(c[3])
        : "r"(a[0]), "r"(a[1]), "r"(a[2]), "r"(a[3]), "r"(b0), "r"(b1));
}

// ============================================================
// Kernel: split weights into bf16 hi/lo. which: 0 = W2, 1 = W3.
// ============================================================
__global__ void prep_split_kernel(const float* __restrict__ src, int n, int which, int base) {
    int i = base + blockIdx.x*256 + threadIdx.x;
    if (i >= n) return;
    float v = src[i];
    __nv_bfloat16 h = __float2bfloat16_rn(v);
    float r = v - __bfloat162float(h);
    __nv_bfloat16 l = __float2bfloat16_rn(r);
    if (which == 0) { g_W2hi[i] = __bfloat16_as_ushort(h); g_W2lo[i] = __bfloat16_as_ushort(l); }
    else            { g_W3hi[i] = __bfloat16_as_ushort(h); g_W3lo[i] = __bfloat16_as_ushort(l); }
}

// ============================================================
// Kernel: farthest point sampling (R14 single-barrier version).
// ============================================================
__global__ __launch_bounds__(512) void fps_kernel(const float* __restrict__ pc,
                                                  float* __restrict__ out_centers) {
    int b = blockIdx.x;
    const float* p = pc + (size_t)b*Nn*3;
    int t = threadIdx.x;
    int lane = t & 31;

    __shared__ unsigned long long s_pk[Gg];
    for (int i = t; i < Gg; i += 512) s_pk[i] = 0ull;

    float px[16], py[16], pz[16], dist[16];
#pragma unroll
    for (int j = 0; j < 16; j++) {
        int idx = t + j*512;
        px[j] = p[idx*3+0]; py[j] = p[idx*3+1]; pz[j] = p[idx*3+2];
        dist[j] = F_INF;
    }

    float cx = p[0], cy = p[1], cz = p[2];
    if (t == 0) {
        int o = (b*Gg + 0)*3;
        g_centers[o] = cx; g_centers[o+1] = cy; g_centers[o+2] = cz;
        out_centers[o] = cx; out_centers[o+1] = cy; out_centers[o+2] = cz;
    }
    __syncthreads();

    for (int g = 1; g < Gg; g++) {
        float best = -1.0f; int bi = 0;
#pragma unroll
        for (int j = 0; j < 16; j++) {
            float dx = px[j]-cx, dy = py[j]-cy, dz = pz[j]-cz;
            float d = __fadd_rn(__fadd_rn(__fmul_rn(dx,dx), __fmul_rn(dy,dy)), __fmul_rn(dz,dz));
            float nd = fminf(dist[j], d);
            dist[j] = nd;
            if (nd > best) { best = nd; bi = t + j*512; }
        }
#pragma unroll
        for (int o = 16; o; o >>= 1) {
            float ov = __shfl_down_sync(0xffffffffu, best, o);
            int   oi = __shfl_down_sync(0xffffffffu, bi,   o);
            if (ov > best || (ov == best && oi < bi)) { best = ov; bi = oi; }
        }
        if (lane == 0) {
            unsigned long long pk =
                ((unsigned long long)__float_as_uint(best) << 32) | (unsigned)(~bi);
            atomicMax(&s_pk[g], pk);
        }
        __syncthreads();
        unsigned long long pk = s_pk[g];
        int sb = (int)(~(unsigned)pk);
        cx = __ldg(&p[sb*3+0]); cy = __ldg(&p[sb*3+1]); cz = __ldg(&p[sb*3+2]);
        if (t == 0) {
            int o = (b*Gg + g)*3;
            g_centers[o] = cx; g_centers[o+1] = cy; g_centers[o+2] = cz;
            out_centers[o] = cx; out_centers[o+1] = cy; out_centers[o+2] = cz;
        }
    }
}

// ============================================================
// Kernel: KNN + gather + 9-moment partials.
// NEW: single-barrier rounds via packed atomicMin into s_pk[r]
// (dist_bits<<32 | idx -> min dist, ties to smallest idx).
// ============================================================
__global__ __launch_bounds__(256) void knn_kernel(const float* __restrict__ pc) {
    int bg = blockIdx.x;
    int b  = bg >> 9;
    const float* p = pc + (size_t)b*Nn*3;
    int t = threadIdx.x;
    int lane = t & 31;

    float cx = g_centers[bg*3+0], cy = g_centers[bg*3+1], cz = g_centers[bg*3+2];

    __shared__ unsigned long long s_pk[32];
    if (t < 32) s_pk[t] = 0xffffffffffffffffull;

    float dl[32];
    float mv = F_INF; int mi = 0x3fffffff;
#pragma unroll
    for (int j = 0; j < 32; j++) {
        int idx = t + j*256;
        float dx = p[idx*3+0]-cx, dy = p[idx*3+1]-cy, dz = p[idx*3+2]-cz;
        float d = fmaf(dx,dx, fmaf(dy,dy, dz*dz));
        dl[j] = d;
        if (d < mv) { mv = d; mi = idx; }
    }
    __syncthreads();

#pragma unroll 1
    for (int r = 0; r < 32; r++) {
        float v = mv; int id = mi;
#pragma unroll
        for (int o = 16; o; o >>= 1) {
            float ov = __shfl_down_sync(0xffffffffu, v,  o);
            int   oi = __shfl_down_sync(0xffffffffu, id, o);
            if (ov < v || (ov == v && oi < id)) { v = ov; id = oi; }
        }
        if (lane == 0) {
            unsigned long long pk =
                ((unsigned long long)__float_as_uint(v) << 32) | (unsigned)id;
            atomicMin(&s_pk[r], pk);
        }
        __syncthreads();
        int best = (int)(unsigned)s_pk[r];
        if ((best & 255) == t) {       // owner: invalidate + rescan (before its
                                       // warp's next-round reduction, program order)
#pragma unroll
            for (int j = 0; j < 32; j++) if (t + j*256 == best) dl[j] = F_INF;
            mv = F_INF; mi = 0x3fffffff;
#pragma unroll
            for (int j = 0; j < 32; j++) { if (dl[j] < mv) { mv = dl[j]; mi = t + j*256; } }
        }
    }

    if (t < 32) {
        int pi = (int)(unsigned)s_pk[t];
        float gx = p[pi*3+0]-cx, gy = p[pi*3+1]-cy, gz = p[pi*3+2]-cz;
        int go = (bg*32 + t)*3;
        g_grouped[go+0] = gx; g_grouped[go+1] = gy; g_grouped[go+2] = gz;
        float s[9] = {gx, gy, gz, gx*gx, gy*gy, gz*gz, gx*gy, gx*gz, gy*gz};
#pragma unroll
        for (int q = 0; q < 9; q++) {
#pragma unroll
            for (int o = 16; o; o >>= 1) s[q] += __shfl_down_sync(0xffffffffu, s[q], o);
        }
        if (t == 0) {
#pragma unroll
            for (int q = 0; q < 9; q++) g_xpart[bg*9 + q] = s[q];
        }
    }
}

// ============================================================
// Kernel: reduce x-moment partials (9 blocks)
// ============================================================
__global__ __launch_bounds__(256) void reduce_x_kernel() {
    __shared__ double sm[256];
    int s = blockIdx.x;
    double a = 0.0;
    for (int i = threadIdx.x; i < NBG; i += 256) a += (double)g_xpart[i*9 + s];
    sm[threadIdx.x] = a; __syncthreads();
    for (int o = 128; o; o >>= 1) {
        if (threadIdx.x < o) sm[threadIdx.x] += sm[threadIdx.x + o];
        __syncthreads();
    }
    if (threadIdx.x == 0) g_xstats[s] = sm[0];
}

// ============================================================
// Kernel: fold BN1 exactly into layer-1 affine
// ============================================================
__global__ void fold1_kernel(const float* __restrict__ W1, const float* __restrict__ b1,
                             const float* __restrict__ g1, const float* __restrict__ be1) {
    int d = threadIdx.x;
    double inv = 1.0 / (double)NPTS;
    double Ex = g_xstats[0]*inv, Ey = g_xstats[1]*inv, Ez = g_xstats[2]*inv;
    double Cxx = g_xstats[3]*inv - Ex*Ex;
    double Cyy = g_xstats[4]*inv - Ey*Ey;
    double Czz = g_xstats[5]*inv - Ez*Ez;
    double Cxy = g_xstats[6]*inv - Ex*Ey;
    double Cxz = g_xstats[7]*inv - Ex*Ez;
    double Cyz = g_xstats[8]*inv - Ey*Ez;
    double w0 = W1[d*3+0], w1 = W1[d*3+1], w2 = W1[d*3+2];
    double mu  = w0*Ex + w1*Ey + w2*Ez + (double)b1[d];
    double var = w0*w0*Cxx + w1*w1*Cyy + w2*w2*Czz + 2.0*(w0*w1*Cxy + w0*w2*Cxz + w1*w2*Cyz);
    if (var < 0.0) var = 0.0;
    double sc = (double)g1[d] / sqrt(var + 1e-5);
    g_W1f[d*4+0] = (float)(w0*sc);
    g_W1f[d*4+1] = (float)(w1*sc);
    g_W1f[d*4+2] = (float)(w2*sc);
    g_W1f[d*4+3] = (float)((double)b1[d]*sc + (double)be1[d] - mu*sc);
}

// ---------------- shared MMA tile constants ----------------
#define LDA 40              // bf16 elements per smem row (32 + 8 pad) -> 80B stride
__device__ __forceinline__ void split_store(char* hi, char* lo, uint32_t boff,
                                            float a0, float a1, float a2, float a3) {
    __nv_bfloat16 h0 = __float2bfloat16_rn(a0), h1 = __float2bfloat16_rn(a1);
    __nv_bfloat16 h2 = __float2bfloat16_rn(a2), h3 = __float2bfloat16_rn(a3);
    __nv_bfloat16 l0 = __float2bfloat16_rn(a0 - __bfloat162float(h0));
    __nv_bfloat16 l1 = __float2bfloat16_rn(a1 - __bfloat162float(h1));
    __nv_bfloat16 l2 = __float2bfloat16_rn(a2 - __bfloat162float(h2));
    __nv_bfloat16 l3 = __float2bfloat16_rn(a3 - __bfloat162float(h3));
    uint32_t hA = ((uint32_t)__bfloat16_as_ushort(h1) << 16) | __bfloat16_as_ushort(h0);
    uint32_t hB = ((uint32_t)__bfloat16_as_ushort(h3) << 16) | __bfloat16_as_ushort(h2);
    uint32_t lA = ((uint32_t)__bfloat16_as_ushort(l1) << 16) | __bfloat16_as_ushort(l0);
    uint32_t lB = ((uint32_t)__bfloat16_as_ushort(l3) << 16) | __bfloat16_as_ushort(l2);
    *(uint2*)(hi + boff) = make_uint2(hA, hB);
    *(uint2*)(lo + boff) = make_uint2(lA, lB);
}

// ============================================================
// Kernel: pass A on mma.sync bf16 3-split (R4 configuration).
// ============================================================
__global__ __launch_bounds__(256) void passA_mma(void) {
    __shared__ __align__(16) unsigned short sAh[128*LDA], sAl[128*LDA];
    __shared__ __align__(16) unsigned short sBh[64*LDA],  sBl[64*LDA];
    __shared__ float s_w1[512];
    __shared__ float s_g[384];
    __shared__ float s_redS[256], s_redQ[256];

    int tid = threadIdx.x, lane = tid & 31, wid = tid >> 5;
    int wm = wid >> 1, wn = wid & 1;
    int cb = blockIdx.x;            // 0..3
    int rb = blockIdx.y;            // 0..2047
    int r0 = rb*128, c0 = cb*64;

    for (int i = tid; i < 384; i += 256) s_g[i] = g_grouped[(size_t)r0*3 + i];
    s_w1[tid] = g_W1f[tid]; s_w1[tid+256] = g_W1f[tid+256];

    float acc[2][4][4];
#pragma unroll
    for (int a = 0; a < 2; a++)
#pragma unroll
        for (int b = 0; b < 4; b++)
#pragma unroll
            for (int c = 0; c < 4; c++) acc[a][b][c] = 0.f;

    uint32_t aHiB = smem_u32(sAh) + ((wm*32 + (lane & 15))*LDA + ((lane >> 4)*8))*2;
    uint32_t aLoB = smem_u32(sAl) + ((wm*32 + (lane & 15))*LDA + ((lane >> 4)*8))*2;
    uint32_t bHiB = smem_u32(sBh) + ((wn*32 + (lane & 15))*LDA + ((lane >> 4)*8))*2;
    uint32_t bLoB = smem_u32(sBl) + ((wn*32 + (lane & 15))*LDA + ((lane >> 4)*8))*2;

#pragma unroll 1
    for (int kc = 0; kc < 4; kc++) {
        __syncthreads();
        int k0 = kc*32;
#pragma unroll
        for (int i = 0; i < 4; i++) {
            int idx = i*256 + tid;
            int row = idx >> 3;
            int ch4 = (idx & 7)*4;
            float gx = s_g[row*3+0], gy = s_g[row*3+1], gz = s_g[row*3+2];
            float v[4];
#pragma unroll
            for (int q = 0; q < 4; q++) {
                int c = k0 + ch4 + q;
                v[q] = fmaxf(s_w1[c*4+0]*gx + s_w1[c*4+1]*gy + s_w1[c*4+2]*gz + s_w1[c*4+3], 0.f);
            }
            split_store((char*)sAh, (char*)sAl, (uint32_t)(row*LDA + ch4)*2, v[0], v[1], v[2], v[3]);
        }
        {
            int row = tid >> 2, seg = tid & 3;
            uint4 vh = *(const uint4*)&g_W2hi[(c0 + row)*128 + k0 + seg*8];
            uint4 vl = *(const uint4*)&g_W2lo[(c0 + row)*128 + k0 + seg*8];
            *(uint4*)((char*)sBh + row*LDA*2 + seg*16) = vh;
            *(uint4*)((char*)sBl + row*LDA*2 + seg*16) = vl;
        }
        __syncthreads();

#pragma unroll
        for (int k16 = 0; k16 < 2; k16++) {
            uint32_t ah[2][4], al[2][4], bh[2][4], bl[2][4];
#pragma unroll
            for (int mt = 0; mt < 2; mt++) {
                ldsm4(ah[mt], aHiB + mt*16*LDA*2 + k16*32);
                ldsm4(al[mt], aLoB + mt*16*LDA*2 + k16*32);
            }
#pragma unroll
            for (int np = 0; np < 2; np++) {
                ldsm4(bh[np], bHiB + np*16*LDA*2 + k16*32);
                ldsm4(bl[np], bLoB + np*16*LDA*2 + k16*32);
            }
#pragma unroll
            for (int mt = 0; mt < 2; mt++)
#pragma unroll
                for (int np = 0; np < 2; np++) {
                    mma_bf16(acc[mt][np*2+0], ah[mt], bh[np][0], bh[np][2]);
                    mma_bf16(acc[mt][np*2+1], ah[mt], bh[np][1], bh[np][3]);
                    mma_bf16(acc[mt][np*2+0], al[mt], bh[np][0], bh[np][2]);
                    mma_bf16(acc[mt][np*2+1], al[mt], bh[np][1], bh[np][3]);
                    mma_bf16(acc[mt][np*2+0], ah[mt], bl[np][0], bl[np][2]);
                    mma_bf16(acc[mt][np*2+1], ah[mt], bl[np][1], bl[np][3]);
                }
        }
    }

    int rbase = r0 + wm*32 + (lane >> 2);
    int cbase = c0 + wn*32 + 2*(lane & 3);
#pragma unroll
    for (int mt = 0; mt < 2; mt++)
#pragma unroll
        for (int nt = 0; nt < 4; nt++) {
            int row = rbase + mt*16;
            int col = cbase + nt*8;
            *(float2*)&g_h2[(size_t)row*256 + col]     = make_float2(acc[mt][nt][0], acc[mt][nt][1]);
            *(float2*)&g_h2[(size_t)(row+8)*256 + col] = make_float2(acc[mt][nt][2], acc[mt][nt][3]);
        }
#pragma unroll
    for (int nt = 0; nt < 4; nt++) {
        float s0 = 0.f, s1 = 0.f, q0 = 0.f, q1 = 0.f;
#pragma unroll
        for (int mt = 0; mt < 2; mt++) {
            s0 += acc[mt][nt][0] + acc[mt][nt][2];
            s1 += acc[mt][nt][1] + acc[mt][nt][3];
            q0 += acc[mt][nt][0]*acc[mt][nt][0] + acc[mt][nt][2]*acc[mt][nt][2];
            q1 += acc[mt][nt][1]*acc[mt][nt][1] + acc[mt][nt][3]*acc[mt][nt][3];
        }
#pragma unroll
        for (int off = 4; off < 32; off <<= 1) {
            s0 += __shfl_xor_sync(0xffffffffu, s0, off);
            s1 += __shfl_xor_sync(0xffffffffu, s1, off);
            q0 += __shfl_xor_sync(0xffffffffu, q0, off);
            q1 += __shfl_xor_sync(0xffffffffu, q1, off);
        }
        if (lane < 4) {
            int cl = wn*32 + nt*8 + 2*lane;
            s_redS[wm*64 + cl] = s0;   s_redS[wm*64 + cl + 1] = s1;
            s_redQ[wm*64 + cl] = q0;   s_redQ[wm*64 + cl + 1] = q1;
        }
    }
    __syncthreads();
    if (tid < 64) {
        float S = 0.f, Q = 0.f;
#pragma unroll
        for (int w = 0; w < 4; w++) { S += s_redS[w*64 + tid]; Q += s_redQ[w*64 + tid]; }
        g_h2sum[(c0 + tid)*2048 + rb] = S;
        g_h2sq [(c0 + tid)*2048 + rb] = Q;
    }
}

// ============================================================
// Kernel: BN2 stats reduce
// ============================================================
__global__ __launch_bounds__(256) void bn2_kernel(const float* __restrict__ g2,
                                                  const float* __restrict__ be2) {
    __shared__ double sm[256];
    __shared__ double sq[256];
    int ch = blockIdx.x;
    double a = 0.0, q = 0.0;
    for (int i = threadIdx.x; i < 2048; i += 256) {
        a += (double)g_h2sum[ch*2048 + i];
        q += (double)g_h2sq[ch*2048 + i];
    }
    sm[threadIdx.x] = a; sq[threadIdx.x] = q; __syncthreads();
    for (int o = 128; o; o >>= 1) {
        if (threadIdx.x < o) { sm[threadIdx.x] += sm[threadIdx.x+o]; sq[threadIdx.x] += sq[threadIdx.x+o]; }
        __syncthreads();
    }
    if (threadIdx.x == 0) {
        double mu  = sm[0] / (double)NPTS;
        double var = sq[0] / (double)NPTS - mu*mu;
        if (var < 0.0) var = 0.0;
        double sc = (double)g2[ch] / sqrt(var + 1e-5);
        g_bn2[ch]       = (float)sc;
        g_bn2[256 + ch] = (float)((double)be2[ch] - mu*sc);
    }
}

// ============================================================
// Kernel: pass B on mma.sync bf16 3-split (R14 configuration).
// ============================================================
__global__ __launch_bounds__(256) void passB_mma(const float* __restrict__ b3,
                                                 float* __restrict__ out_tokens) {
    __shared__ __align__(16) unsigned short sAh[128*LDA], sAl[128*LDA];
    __shared__ __align__(16) unsigned short sBh[64*LDA],  sBl[64*LDA];
    __shared__ float s_bn[512];

    int tid = threadIdx.x, lane = tid & 31, wid = tid >> 5;
    int wm = wid >> 1, wn = wid & 1;
    int cb = blockIdx.x;            // 0..5
    int rb = blockIdx.y;            // 0..2047
    int r0 = rb*128, c0 = cb*64;

    s_bn[tid] = g_bn2[tid]; s_bn[tid+256] = g_bn2[tid+256];

    float acc[2][4][4];
#pragma unroll
    for (int a = 0; a < 2; a++)
#pragma unroll
        for (int b = 0; b < 4; b++)
#pragma unroll
            for (int c = 0; c < 4; c++) acc[a][b][c] = 0.f;

    uint32_t aHiB = smem_u32(sAh) + ((wm*32 + (lane & 15))*LDA + ((lane >> 4)*8))*2;
    uint32_t aLoB = smem_u32(sAl) + ((wm*32 + (lane & 15))*LDA + ((lane >> 4)*8))*2;
    uint32_t bHiB = smem_u32(sBh) + ((wn*32 + (lane & 15))*LDA + ((lane >> 4)*8))*2;
    uint32_t bLoB = smem_u32(sBl) + ((wn*32 + (lane & 15))*LDA + ((lane >> 4)*8))*2;

#pragma unroll 1
    for (int kc = 0; kc < 8; kc++) {
        __syncthreads();
        int k0 = kc*32;
#pragma unroll
        for (int i = 0; i < 4; i++) {
            int idx = i*256 + tid;
            int row = idx >> 3;
            int q4  = (idx & 7)*4;
            float4 h = *(const float4*)&g_h2[(size_t)(r0 + row)*256 + k0 + q4];
            int ch = k0 + q4;
            float a0 = fmaxf(h.x*s_bn[ch+0] + s_bn[256+ch+0], 0.f);
            float a1 = fmaxf(h.y*s_bn[ch+1] + s_bn[256+ch+1], 0.f);
            float a2 = fmaxf(h.z*s_bn[ch+2] + s_bn[256+ch+2], 0.f);
            float a3 = fmaxf(h.w*s_bn[ch+3] + s_bn[256+ch+3], 0.f);
            split_store((char*)sAh, (char*)sAl, (uint32_t)(row*LDA + q4)*2, a0, a1, a2, a3);
        }
        {
            int row = tid >> 2, seg = tid & 3;
            uint4 vh = *(const uint4*)&g_W3hi[(c0 + row)*256 + k0 + seg*8];
            uint4 vl = *(const uint4*)&g_W3lo[(c0 + row)*256 + k0 + seg*8];
            *(uint4*)((char*)sBh + row*LDA*2 + seg*16) = vh;
            *(uint4*)((char*)sBl + row*LDA*2 + seg*16) = vl;
        }
        __syncthreads();

#pragma unroll
        for (int k16 = 0; k16 < 2; k16++) {
            uint32_t ah[2][4], al[2][4], bh[2][4], bl[2][4];
#pragma unroll
            for (int mt = 0; mt < 2; mt++) {
                ldsm4(ah[mt], aHiB + mt*16*LDA*2 + k16*32);
                ldsm4(al[mt], aLoB + mt*16*LDA*2 + k16*32);
            }
#pragma unroll
            for (int np = 0; np < 2; np++) {
                ldsm4(bh[np], bHiB + np*16*LDA*2 + k16*32);
                ldsm4(bl[np], bLoB + np*16*LDA*2 + k16*32);
            }
#pragma unroll
            for (int mt = 0; mt < 2; mt++)
#pragma unroll
                for (int np = 0; np < 2; np++) {
                    mma_bf16(acc[mt][np*2+0], ah[mt], bh[np][0], bh[np][2]);
                    mma_bf16(acc[mt][np*2+1], ah[mt], bh[np][1], bh[np][3]);
                    mma_bf16(acc[mt][np*2+0], al[mt], bh[np][0], bh[np][2]);
                    mma_bf16(acc[mt][np*2+1], al[mt], bh[np][1], bh[np][3]);
                    mma_bf16(acc[mt][np*2+0], ah[mt], bl[np][0], bl[np][2]);
                    mma_bf16(acc[mt][np*2+1], ah[mt], bl[np][1], bl[np][3]);
                }
        }
    }

    int bg = rb*4 + wm;
#pragma unroll
    for (int nt = 0; nt < 4; nt++) {
        float m0 = fmaxf(fmaxf(acc[0][nt][0], acc[0][nt][2]), fmaxf(acc[1][nt][0], acc[1][nt][2]));
        float m1 = fmaxf(fmaxf(acc[0][nt][1], acc[0][nt][3]), fmaxf(acc[1][nt][1], acc[1][nt][3]));
#pragma unroll
        for (int off = 4; off < 32; off <<= 1) {
            m0 = fmaxf(m0, __shfl_xor_sync(0xffffffffu, m0, off));
            m1 = fmaxf(m1, __shfl_xor_sync(0xffffffffu, m1, off));
        }
        if (lane < 4) {
            int col = c0 + wn*32 + nt*8 + 2*lane;
            out_tokens[(size_t)bg*Dd + col]     = m0 + b3[col];
            out_tokens[(size_t)bg*Dd + col + 1] = m1 + b3[col + 1];
        }
    }
}

// ============================================================
extern "C" void kernel_launch(void* const* d_in, const int* in_sizes, int n_in,
                              void* d_out, int out_size) {
    const float* pc  = (const float*)d_in[0];
    const float* W1  = (const float*)d_in[1];
    const float* b1  = (const float*)d_in[2];
    const float* g1  = (const float*)d_in[3];
    const float* be1 = (const float*)d_in[4];
    const float* W2  = (const float*)d_in[5];
    // d_in[6] = b2 (cancels under BN2)
    const float* g2  = (const float*)d_in[7];
    const float* be2 = (const float*)d_in[8];
    const float* W3  = (const float*)d_in[9];
    const float* b3  = (const float*)d_in[10];

    float* out_tokens  = (float*)d_out;
    float* out_centers = (float*)d_out + (size_t)Bb*Gg*Dd;

    // knn in profiled slot #4
    prep_split_kernel<<<128, 256>>>(W2, 256*128, 0, 0);
    prep_split_kernel<<<384, 256>>>(W3, 384*256, 1, 0);
    fps_kernel<<<Bb, 512>>>(pc, out_centers);
    knn_kernel<<<NBG, 256>>>(pc);                        // launch #4 -> profiled
    reduce_x_kernel<<<9, 256>>>();
    fold1_kernel<<<1, 128>>>(W1, b1, g1, be1);
    passA_mma<<<dim3(4, 2048), 256>>>();
    bn2_kernel<<<256, 256>>>(g2, be2);
    passB_mma<<<dim3(6, 2048), 256>>>(b3, out_tokens);
}